// round 12
// baseline (speedup 1.0000x reference)
#include <cuda_runtime.h>
#include <cstdint>

#define NUM_ENTS   80000
#define NUM_WORDS  20000
#define N_NODES    (NUM_ENTS + NUM_WORDS)
#define H          200
#define NB         100
#define SUB        2
#define NREL       16
#define NEDGE      300000
#define RRELU_SLOPE 0.22916666666666666f   // (1/8 + 1/3)/2

#define CAP 64     // bucket capacity per destination (Poisson(3): P(>=64) ~ 1e-60)

// Scratch (device globals — zero-initialized at module load).
// INVARIANT: g_count is all-zero at the start of every kernel_launch call:
// it starts zeroed, and pull_kernel resets each entry after consuming it.
__device__ int g_count[NUM_ENTS];
__device__ int g_edges[(size_t)NUM_ENTS * CAP];         // packed (src | etype<<17)

// ---------------------------------------------------------------------------
// Kernel 1: scatter edges into per-destination buckets (default cache policy —
// pull re-reads these from L2).
// Only destinations < NUM_ENTS matter (word-node rows are discarded downstream).
// ---------------------------------------------------------------------------
__global__ void scatter_kernel(const int* __restrict__ src,
                               const int* __restrict__ dst,
                               const int* __restrict__ etype) {
    int i = blockIdx.x * blockDim.x + threadIdx.x;
    if (i >= NEDGE) return;
    int d = dst[i];
    if (d >= NUM_ENTS) return;
    int pos = atomicAdd(&g_count[d], 1);
    if (pos < CAP) {
        int packed = src[i] | (etype[i] << 17);   // src < 100000 fits in 17 bits
        g_edges[(size_t)d * CAP + pos] = packed;
    }
}

// ---------------------------------------------------------------------------
// Kernel 2: pull + finalize. One warp per entity node, simple edge loop
// (best measured structure). Output stores are streaming (__stcs): written
// once, never re-read — keeps the h working set + buckets L2-resident.
// Resets g_count[node] to 0 to restore the all-zero invariant.
// ---------------------------------------------------------------------------
__global__ void __launch_bounds__(256)
pull_kernel(const float* __restrict__ dyn,
            const float* __restrict__ words,
            const float* __restrict__ weight,
            float* __restrict__ out) {
    int node = (blockIdx.x * blockDim.x + threadIdx.x) >> 5;
    int lane = threadIdx.x & 31;
    if (node >= NUM_ENTS) return;

    int cnt = g_count[node];
    if (lane == 0) g_count[node] = 0;            // restore invariant
    int n = min(cnt, CAP);
    const int* bucket = g_edges + (size_t)node * CAP;

    const bool c1ok = (lane < H / 4 - 32);       // lanes 0..17 also cover chunk lane+32
    float4 acc0 = make_float4(0.f, 0.f, 0.f, 0.f);
    float4 acc1 = make_float4(0.f, 0.f, 0.f, 0.f);

    for (int e = 0; e < n; ++e) {
        int packed = bucket[e];                  // uniform address -> broadcast
        int s = packed & 0x1FFFF;
        int r = packed >> 17;

        const float* hbase = (s < NUM_ENTS) ? (dyn + (size_t)s * H)
                                            : (words + (size_t)(s - NUM_ENTS) * H);
        const float4* hrow = (const float4*)hbase;
        const float4* W    = (const float4*)(weight + (size_t)r * NB * SUB * SUB);

        {   // chunk c0 = lane : blocks 2*lane, 2*lane+1
            float4 h  = __ldg(&hrow[lane]);
            float4 w0 = __ldg(&W[2 * lane]);
            float4 w1 = __ldg(&W[2 * lane + 1]);
            acc0.x = fmaf(h.x, w0.x, fmaf(h.y, w0.z, acc0.x));
            acc0.y = fmaf(h.x, w0.y, fmaf(h.y, w0.w, acc0.y));
            acc0.z = fmaf(h.z, w1.x, fmaf(h.w, w1.z, acc0.z));
            acc0.w = fmaf(h.z, w1.y, fmaf(h.w, w1.w, acc0.w));
        }
        if (c1ok) { // chunk c1 = lane + 32
            int c = lane + 32;
            float4 h  = __ldg(&hrow[c]);
            float4 w0 = __ldg(&W[2 * c]);
            float4 w1 = __ldg(&W[2 * c + 1]);
            acc1.x = fmaf(h.x, w0.x, fmaf(h.y, w0.z, acc1.x));
            acc1.y = fmaf(h.x, w0.y, fmaf(h.y, w0.w, acc1.y));
            acc1.z = fmaf(h.z, w1.x, fmaf(h.w, w1.z, acc1.z));
            acc1.w = fmaf(h.z, w1.y, fmaf(h.w, w1.w, acc1.w));
        }
    }

    // finalize: /indeg, rrelu, L2-normalize, dual write
    float normf = (cnt > 0) ? (1.0f / (float)cnt) : 0.0f;

    acc0.x *= normf; acc0.y *= normf; acc0.z *= normf; acc0.w *= normf;
    acc1.x *= normf; acc1.y *= normf; acc1.z *= normf; acc1.w *= normf;

    acc0.x = (acc0.x >= 0.f) ? acc0.x : acc0.x * RRELU_SLOPE;
    acc0.y = (acc0.y >= 0.f) ? acc0.y : acc0.y * RRELU_SLOPE;
    acc0.z = (acc0.z >= 0.f) ? acc0.z : acc0.z * RRELU_SLOPE;
    acc0.w = (acc0.w >= 0.f) ? acc0.w : acc0.w * RRELU_SLOPE;
    acc1.x = (acc1.x >= 0.f) ? acc1.x : acc1.x * RRELU_SLOPE;
    acc1.y = (acc1.y >= 0.f) ? acc1.y : acc1.y * RRELU_SLOPE;
    acc1.z = (acc1.z >= 0.f) ? acc1.z : acc1.z * RRELU_SLOPE;
    acc1.w = (acc1.w >= 0.f) ? acc1.w : acc1.w * RRELU_SLOPE;

    float sumsq = acc0.x * acc0.x + acc0.y * acc0.y + acc0.z * acc0.z + acc0.w * acc0.w;
    if (c1ok)
        sumsq += acc1.x * acc1.x + acc1.y * acc1.y + acc1.z * acc1.z + acc1.w * acc1.w;

    #pragma unroll
    for (int off = 16; off > 0; off >>= 1)
        sumsq += __shfl_xor_sync(0xFFFFFFFFu, sumsq, off);

    float inv = 1.0f / fmaxf(sqrtf(sumsq), 1e-12f);

    acc0.x *= inv; acc0.y *= inv; acc0.z *= inv; acc0.w *= inv;
    acc1.x *= inv; acc1.y *= inv; acc1.z *= inv; acc1.w *= inv;

    // Streaming stores: outputs are write-once, never re-read.
    float4* o0 = (float4*)(out + (size_t)node * H);
    float4* o1 = (float4*)(out + (size_t)NUM_ENTS * H + (size_t)node * H);
    __stcs(&o0[lane], acc0);
    __stcs(&o1[lane], acc0);
    if (c1ok) {
        __stcs(&o0[lane + 32], acc1);
        __stcs(&o1[lane + 32], acc1);
    }
}

// ---------------------------------------------------------------------------
extern "C" void kernel_launch(void* const* d_in, const int* in_sizes, int n_in,
                              void* d_out, int out_size) {
    const float* dyn    = (const float*)d_in[0];
    const float* words  = (const float*)d_in[1];
    const float* weight = (const float*)d_in[2];
    const int*   src    = (const int*)d_in[3];
    const int*   dst    = (const int*)d_in[4];
    const int*   etype  = (const int*)d_in[5];
    float* out = (float*)d_out;

    (void)in_sizes; (void)n_in; (void)out_size;

    scatter_kernel<<<(NEDGE + 255) / 256, 256>>>(src, dst, etype);
    // one warp per entity node: 80000 warps, 8 per block
    pull_kernel<<<(NUM_ENTS + 7) / 8, 256>>>(dyn, words, weight, out);
}

// round 14
// speedup vs baseline: 1.8033x; 1.8033x over previous
#include <cuda_runtime.h>
#include <cstdint>

#define NUM_ENTS   80000
#define NUM_WORDS  20000
#define N_NODES    (NUM_ENTS + NUM_WORDS)
#define H          200
#define NB         100
#define SUB        2
#define NREL       16
#define NEDGE      300000
#define RRELU_SLOPE 0.22916666666666666f   // (1/8 + 1/3)/2

#define CAP 64     // bucket capacity per destination node (Poisson(3): P(>=64) ~ 1e-60)

// Scratch (device globals — no allocations allowed)
__device__ int g_count[NUM_ENTS];                       // in-degree / scatter cursor
__device__ int g_edges[(size_t)NUM_ENTS * CAP];         // packed (src | etype<<17), 20.5 MB

// ---------------------------------------------------------------------------
// Kernel 1: zero the counters
// ---------------------------------------------------------------------------
__global__ void zero_counts_kernel() {
    int i = blockIdx.x * blockDim.x + threadIdx.x;
    if (i < NUM_ENTS) g_count[i] = 0;
}

// ---------------------------------------------------------------------------
// Kernel 2: scatter edges into per-destination buckets.
// Only destinations < NUM_ENTS matter (word-node rows are discarded downstream).
// ---------------------------------------------------------------------------
__global__ void scatter_kernel(const int* __restrict__ src,
                               const int* __restrict__ dst,
                               const int* __restrict__ etype) {
    int i = blockIdx.x * blockDim.x + threadIdx.x;
    if (i >= NEDGE) return;
    int d = dst[i];
    if (d >= NUM_ENTS) return;
    int pos = atomicAdd(&g_count[d], 1);
    if (pos < CAP) {
        int packed = src[i] | (etype[i] << 17);   // src < 100000 fits in 17 bits
        g_edges[(size_t)d * CAP + pos] = packed;
    }
}

// ---------------------------------------------------------------------------
// Kernel 3: pull + finalize. One warp per entity node.
//   acc[b,o] = sum_edges  h[src][2b+i] * W[etype][b][i][o]
//   then: /indeg, rrelu, L2-normalize, write both output copies.
// All accumulation in registers — no global atomics, no scratch accumulator.
// ---------------------------------------------------------------------------
__global__ void __launch_bounds__(256)
pull_kernel(const float* __restrict__ dyn,
            const float* __restrict__ words,
            const float* __restrict__ weight,
            float* __restrict__ out) {
    int node = (blockIdx.x * blockDim.x + threadIdx.x) >> 5;
    int lane = threadIdx.x & 31;
    if (node >= NUM_ENTS) return;

    int cnt = g_count[node];
    int n   = min(cnt, CAP);
    const int* bucket = g_edges + (size_t)node * CAP;

    // chunk c0 = lane (always valid, c0 < 50), chunk c1 = lane+32 (valid if < 50)
    const int  c1ok = (lane < H / 4 - 32);   // lane < 18
    float4 acc0 = make_float4(0.f, 0.f, 0.f, 0.f);
    float4 acc1 = make_float4(0.f, 0.f, 0.f, 0.f);

    for (int e = 0; e < n; ++e) {
        int packed = bucket[e];                      // uniform address -> broadcast
        int s = packed & 0x1FFFF;
        int r = packed >> 17;

        const float* hbase = (s < NUM_ENTS) ? (dyn + (size_t)s * H)
                                            : (words + (size_t)(s - NUM_ENTS) * H);
        const float4* hrow = (const float4*)hbase;
        const float4* W    = (const float4*)(weight + (size_t)r * NB * SUB * SUB);

        {   // chunk c0 = lane : blocks 2*lane, 2*lane+1
            float4 h  = __ldg(&hrow[lane]);
            float4 w0 = __ldg(&W[2 * lane]);
            float4 w1 = __ldg(&W[2 * lane + 1]);
            acc0.x = fmaf(h.x, w0.x, fmaf(h.y, w0.z, acc0.x));
            acc0.y = fmaf(h.x, w0.y, fmaf(h.y, w0.w, acc0.y));
            acc0.z = fmaf(h.z, w1.x, fmaf(h.w, w1.z, acc0.z));
            acc0.w = fmaf(h.z, w1.y, fmaf(h.w, w1.w, acc0.w));
        }
        if (c1ok) {   // chunk c1 = lane + 32
            int c = lane + 32;
            float4 h  = __ldg(&hrow[c]);
            float4 w0 = __ldg(&W[2 * c]);
            float4 w1 = __ldg(&W[2 * c + 1]);
            acc1.x = fmaf(h.x, w0.x, fmaf(h.y, w0.z, acc1.x));
            acc1.y = fmaf(h.x, w0.y, fmaf(h.y, w0.w, acc1.y));
            acc1.z = fmaf(h.z, w1.x, fmaf(h.w, w1.z, acc1.z));
            acc1.w = fmaf(h.z, w1.y, fmaf(h.w, w1.w, acc1.w));
        }
    }

    // finalize: scale by 1/indeg, rrelu
    float normf = (cnt > 0) ? (1.0f / (float)cnt) : 0.0f;

    acc0.x *= normf; acc0.y *= normf; acc0.z *= normf; acc0.w *= normf;
    acc1.x *= normf; acc1.y *= normf; acc1.z *= normf; acc1.w *= normf;

    acc0.x = (acc0.x >= 0.f) ? acc0.x : acc0.x * RRELU_SLOPE;
    acc0.y = (acc0.y >= 0.f) ? acc0.y : acc0.y * RRELU_SLOPE;
    acc0.z = (acc0.z >= 0.f) ? acc0.z : acc0.z * RRELU_SLOPE;
    acc0.w = (acc0.w >= 0.f) ? acc0.w : acc0.w * RRELU_SLOPE;
    acc1.x = (acc1.x >= 0.f) ? acc1.x : acc1.x * RRELU_SLOPE;
    acc1.y = (acc1.y >= 0.f) ? acc1.y : acc1.y * RRELU_SLOPE;
    acc1.z = (acc1.z >= 0.f) ? acc1.z : acc1.z * RRELU_SLOPE;
    acc1.w = (acc1.w >= 0.f) ? acc1.w : acc1.w * RRELU_SLOPE;

    float sumsq = acc0.x * acc0.x + acc0.y * acc0.y + acc0.z * acc0.z + acc0.w * acc0.w;
    if (c1ok)
        sumsq += acc1.x * acc1.x + acc1.y * acc1.y + acc1.z * acc1.z + acc1.w * acc1.w;

    #pragma unroll
    for (int off = 16; off > 0; off >>= 1)
        sumsq += __shfl_xor_sync(0xFFFFFFFFu, sumsq, off);

    float inv = 1.0f / fmaxf(sqrtf(sumsq), 1e-12f);

    acc0.x *= inv; acc0.y *= inv; acc0.z *= inv; acc0.w *= inv;
    acc1.x *= inv; acc1.y *= inv; acc1.z *= inv; acc1.w *= inv;

    float4* o0 = (float4*)(out + (size_t)node * H);
    float4* o1 = (float4*)(out + (size_t)NUM_ENTS * H + (size_t)node * H);
    o0[lane] = acc0;
    o1[lane] = acc0;
    if (c1ok) {
        o0[lane + 32] = acc1;
        o1[lane + 32] = acc1;
    }
}

// ---------------------------------------------------------------------------
extern "C" void kernel_launch(void* const* d_in, const int* in_sizes, int n_in,
                              void* d_out, int out_size) {
    const float* dyn    = (const float*)d_in[0];
    const float* words  = (const float*)d_in[1];
    const float* weight = (const float*)d_in[2];
    const int*   src    = (const int*)d_in[3];
    const int*   dst    = (const int*)d_in[4];
    const int*   etype  = (const int*)d_in[5];
    float* out = (float*)d_out;

    (void)in_sizes; (void)n_in; (void)out_size;

    zero_counts_kernel<<<(NUM_ENTS + 255) / 256, 256>>>();
    scatter_kernel<<<(NEDGE + 255) / 256, 256>>>(src, dst, etype);
    // one warp per entity node: 80000 warps, 8 per block
    pull_kernel<<<(NUM_ENTS + 7) / 8, 256>>>(dyn, words, weight, out);
}